// round 16
// baseline (speedup 1.0000x reference)
#include <cuda_runtime.h>
#include <cuda_fp16.h>
#include <cstdint>

#define LSEQ 4096
#define DM   256
#define BMAX 4
#define KS2  8

// -------- scratch globals --------
__device__ __align__(16) __half g_xh [BMAX * LSEQ * DM];   // fp16 x   [b][l][d]
__device__ __align__(16) __half g_wxt[BMAX * DM * LSEQ];   // fp16 w*x [b][d][l]
__device__ float  g_w  [BMAX * LSEQ];
__device__ float  g_c0p[BMAX * 64 * DM];                   // c0 partials per 64-row slab
__device__ float  g_s0p[BMAX * 64];
__device__ float  g_c0 [BMAX * DM];
__device__ float  g_s0 [BMAX];
__device__ float  g_m1p[(size_t)KS2 * BMAX * DM * DM];     // M1 partials (8.4 MB)
__device__ __align__(16) __half g_m1h[BMAX * DM * DM];     // M1 fp16 (symmetric)
__device__ __align__(16) float g_pe[LSEQ * DM];            // PE table (batch-independent)

#define C_FREQ  (-0.035977892078032f)
#define INV_2PI ( 0.15915494309189535f)
#define PI2_HI  ( 6.28125f)
#define PI2_LO  ( 1.9353071795864769e-3f)

// ---------------- asm helpers ----------------
__device__ __forceinline__ uint32_t smem_u32(const void* p) {
    uint32_t a;
    asm("{ .reg .u64 t; cvta.to.shared.u64 t, %1; cvt.u32.u64 %0, t; }" : "=r"(a) : "l"(p));
    return a;
}
__device__ __forceinline__ void cp_async16(uint32_t dst, const void* src) {
    asm volatile("cp.async.cg.shared.global [%0], [%1], 16;" :: "r"(dst), "l"(src) : "memory");
}
__device__ __forceinline__ void cp_commit() { asm volatile("cp.async.commit_group;" ::: "memory"); }
__device__ __forceinline__ void cp_wait0()  { asm volatile("cp.async.wait_group 0;" ::: "memory"); }
#define CP_WAIT(N) asm volatile("cp.async.wait_group %0;" :: "n"(N) : "memory")

__device__ __forceinline__ void ldsm_x4(uint32_t addr, uint32_t r[4]) {
    asm volatile("ldmatrix.sync.aligned.m8n8.x4.shared.b16 {%0,%1,%2,%3}, [%4];"
        : "=r"(r[0]), "=r"(r[1]), "=r"(r[2]), "=r"(r[3]) : "r"(addr));
}
__device__ __forceinline__ void ldsm_x4t(uint32_t addr, uint32_t r[4]) {
    asm volatile("ldmatrix.sync.aligned.m8n8.x4.trans.shared.b16 {%0,%1,%2,%3}, [%4];"
        : "=r"(r[0]), "=r"(r[1]), "=r"(r[2]), "=r"(r[3]) : "r"(addr));
}
__device__ __forceinline__ void mma_f32(float c[4], const uint32_t a[4],
                                        uint32_t b0, uint32_t b1) {
    asm volatile("mma.sync.aligned.m16n8k16.row.col.f32.f16.f16.f32 "
        "{%0,%1,%2,%3}, {%4,%5,%6,%7}, {%8,%9}, {%0,%1,%2,%3};"
        : "+f"(c[0]), "+f"(c[1]), "+f"(c[2]), "+f"(c[3])
        : "r"(a[0]), "r"(a[1]), "r"(a[2]), "r"(a[3]), "r"(b0), "r"(b1));
}
__device__ __forceinline__ void mma_f16(uint32_t c[2], const uint32_t a[4],
                                        uint32_t b0, uint32_t b1) {
    asm volatile("mma.sync.aligned.m16n8k16.row.col.f16.f16.f16.f16 "
        "{%0,%1}, {%2,%3,%4,%5}, {%6,%7}, {%0,%1};"
        : "+r"(c[0]), "+r"(c[1])
        : "r"(a[0]), "r"(a[1]), "r"(a[2]), "r"(a[3]), "r"(b0), "r"(b1));
}
__device__ __forceinline__ uint32_t pack2f16(float lo, float hi) {
    uint32_t r;
    asm("cvt.rn.f16x2.f32 %0, %1, %2;" : "=r"(r) : "f"(hi), "f"(lo));
    return r;
}

// ========== K1: fused conv + transpose + w + c0/s0 partials + PE table ==========
#define K1_SMEM (64 * 264 * 2 + 64 * 4)
__global__ __launch_bounds__(256) void prep_kernel(const float* __restrict__ x) {
    extern __shared__ char smem[];
    __half* ths = reinterpret_cast<__half*>(smem);
    float*  ws  = reinterpret_cast<float*>(smem + 64 * 264 * 2);
    const int tid = threadIdx.x, wid = tid >> 5, lane = tid & 31;
    const int b = blockIdx.y, bx = blockIdx.x, l0 = bx * 64;
    const float* xs = x + ((size_t)b * LSEQ + l0) * DM;
    __half* xho = g_xh + ((size_t)b * LSEQ + l0) * DM;

    #pragma unroll
    for (int it = 0; it < 8; it++) {
        int r = it * 8 + wid;
        const float4* src = reinterpret_cast<const float4*>(xs + (size_t)r * DM);
        float4 a = src[lane * 2], c = src[lane * 2 + 1];
        uint4 v;
        v.x = pack2f16(a.x, a.y); v.y = pack2f16(a.z, a.w);
        v.z = pack2f16(c.x, c.y); v.w = pack2f16(c.z, c.w);
        *reinterpret_cast<uint4*>(ths + r * 264 + lane * 8) = v;
        reinterpret_cast<uint4*>(xho + (size_t)r * DM)[lane] = v;
        float s = a.x*a.x + a.y*a.y + a.z*a.z + a.w*a.w
                + c.x*c.x + c.y*c.y + c.z*c.z + c.w*c.w;
        #pragma unroll
        for (int m = 16; m > 0; m >>= 1) s += __shfl_xor_sync(0xffffffffu, s, m);
        if (lane == 0) {
            float w = __expf(-0.5f * s);
            ws[r] = w;
            g_w[b * LSEQ + l0 + r] = w;
        }
    }
    __syncthreads();

    // transpose + c0 partial: thread d handles column d
    const int d = tid;
    __half* dst = g_wxt + ((size_t)b * DM + d) * LSEQ + l0;
    float c0part = 0.f;
    #pragma unroll
    for (int q = 0; q < 4; q++) {
        uint32_t pk2[8];
        #pragma unroll
        for (int i = 0; i < 8; i++) {
            int l = q * 16 + 2 * i;
            float f0 = __half2float(ths[(l)     * 264 + d]) * ws[l];
            float f1 = __half2float(ths[(l + 1) * 264 + d]) * ws[l + 1];
            c0part += f0 + f1;
            pk2[i] = pack2f16(f0, f1);
        }
        reinterpret_cast<uint4*>(dst + q * 16)[0] = make_uint4(pk2[0], pk2[1], pk2[2], pk2[3]);
        reinterpret_cast<uint4*>(dst + q * 16)[1] = make_uint4(pk2[4], pk2[5], pk2[6], pk2[7]);
    }
    g_c0p[((size_t)b * 64 + bx) * DM + d] = c0part;

    if (wid == 0) {        // s0 partial
        float s = ws[lane] + ws[lane + 32];
        #pragma unroll
        for (int m = 16; m > 0; m >>= 1) s += __shfl_xor_sync(0xffffffffu, s, m);
        if (lane == 0) g_s0p[b * 64 + bx] = s;
    }

    // PE table (batch-independent): only b==0 CTAs
    if (b == 0) {
        float wf = __expf(C_FREQ * (float)(d & ~1));
        float* pp = g_pe + (size_t)l0 * DM + d;
        #pragma unroll 4
        for (int l = 0; l < 64; l++) {
            float ang = (float)(l0 + l) * wf;
            float k = rintf(ang * INV_2PI);
            float rr = fmaf(-k, PI2_HI, ang); rr = fmaf(-k, PI2_LO, rr);
            pp[(size_t)l * DM] = (d & 1) ? __cosf(rr) : __sinf(rr);
        }
    }
}

// ========== K2: M1 partial = (w X)^T X over 2 chunks of 256 keys ==========
#define G_SMEM 196608
__global__ __launch_bounds__(256, 1) void gemmM1_kernel() {
    extern __shared__ char smem[];
    const uint32_t sb = smem_u32(smem);
    const int tid = threadIdx.x, wid = tid >> 5, lane = tid & 31;
    const int ks = blockIdx.x, half = blockIdx.y, b = blockIdx.z;
    const int lr = lane & 15, lh = lane >> 4, lq = lane >> 2, lc = lane & 3;

    const int wa = (wid & 3) * 64;
    const int wn = (wid >> 2) * 64;
    float acc[4][8][4];
    #pragma unroll
    for (int mt = 0; mt < 4; mt++)
        #pragma unroll
        for (int f = 0; f < 8; f++)
            #pragma unroll
            for (int q = 0; q < 4; q++) acc[mt][f][q] = 0.f;

    const uint32_t As = sb, Bs = sb + 131072;

    for (int sub = 0; sub < 2; sub++) {
        const int jc = (ks * 2 + sub) * 256;
        if (sub) __syncthreads();
        #pragma unroll
        for (int it = 0; it < 32; it++) {
            int idx = it * 256 + tid;
            int r = idx >> 5, g = idx & 31;
            cp_async16(As + r * 512 + (((uint32_t)g ^ (r & 7)) << 4),
                       g_wxt + ((size_t)b * DM + r) * LSEQ + jc + g * 8);
        }
        #pragma unroll
        for (int it = 0; it < 16; it++) {
            int idx = it * 256 + tid;
            int r = idx >> 4, g = idx & 15;
            cp_async16(Bs + r * 256 + (((uint32_t)g ^ (r & 7)) << 4),
                       g_xh + ((size_t)b * LSEQ + jc + r) * DM + half * 128 + g * 8);
        }
        cp_commit(); cp_wait0();
        __syncthreads();

        #pragma unroll
        for (int k16 = 0; k16 < 16; k16++) {
            uint32_t aq[4][4];
            #pragma unroll
            for (int mt = 0; mt < 4; mt++) {
                int ar = wa + 16 * mt + lr;
                ldsm_x4(As + ar * 512 + ((((uint32_t)(2 * k16 + lh)) ^ (ar & 7)) << 4), aq[mt]);
            }
            #pragma unroll
            for (int nt = 0; nt < 4; nt++) {
                int rv = 16 * k16 + lr;
                int cb = (wn >> 3) + 2 * nt + lh;
                uint32_t bv[4];
                ldsm_x4t(Bs + rv * 256 + (((uint32_t)cb ^ (rv & 7)) << 4), bv);
                #pragma unroll
                for (int mt = 0; mt < 4; mt++) {
                    mma_f32(acc[mt][2*nt],     aq[mt], bv[0], bv[1]);
                    mma_f32(acc[mt][2*nt + 1], aq[mt], bv[2], bv[3]);
                }
            }
        }
    }

    #pragma unroll
    for (int mt = 0; mt < 4; mt++) {
        int r0 = wa + 16 * mt + lq;
        #pragma unroll
        for (int f = 0; f < 8; f++) {
            int col = half * 128 + wn + 8 * f + 2 * lc;
            size_t base = (((size_t)ks * BMAX + b) * DM + r0) * DM + col;
            *reinterpret_cast<float2*>(g_m1p + base) =
                make_float2(acc[mt][f][0], acc[mt][f][1]);
            *reinterpret_cast<float2*>(g_m1p + base + (size_t)8 * DM) =
                make_float2(acc[mt][f][2], acc[mt][f][3]);
        }
    }
}

// ========== K3: reduce M1 partials -> fp16, plus c0 and s0 from prep partials ==========
__global__ void reduceM1_kernel() {
    int xb = blockIdx.x, b = blockIdx.y, tid = threadIdx.x;
    if (xb < DM) {
        float s = 0.f;
        #pragma unroll
        for (int ks = 0; ks < KS2; ks++)
            s += g_m1p[(((size_t)ks * BMAX + b) * DM + xb) * DM + tid];
        g_m1h[((size_t)b * DM + xb) * DM + tid] = __float2half(s);
    } else {
        float s = 0.f;
        #pragma unroll
        for (int k = 0; k < 64; k++)
            s += g_c0p[((size_t)b * 64 + k) * DM + tid];
        g_c0[b * DM + tid] = s;
        if (tid < 32) {
            float t = g_s0p[b * 64 + tid] + g_s0p[b * 64 + 32 + tid];
            #pragma unroll
            for (int m = 16; m > 0; m >>= 1) t += __shfl_xor_sync(0xffffffffu, t, m);
            if (tid == 0) g_s0[b] = t;
        }
    }
}

// ========== K4: Y = X M1 (pipelined, f16 accum) + epilogue (PE table) ==========
__global__ __launch_bounds__(256, 1) void yepi_kernel(float* __restrict__ out)
{
    extern __shared__ char smem[];
    const uint32_t sb = smem_u32(smem);
    const int tid = threadIdx.x, wid = tid >> 5, lane = tid & 31;
    const int b = blockIdx.y, row0 = blockIdx.x * 128, m0 = wid * 16;
    const int lr = lane & 15, lh = lane >> 4, lq = lane >> 2, lc = lane & 3;
    const uint32_t Xs = sb, Ms = sb + 65536;

    // group 0: Xs (full) + Ms chunk 0
    #pragma unroll
    for (int it = 0; it < 16; it++) {
        int idx = it * 256 + tid;
        int r = idx >> 5, g = idx & 31;
        cp_async16(Xs + r * 512 + (((uint32_t)g ^ (r & 7)) << 4),
                   g_xh + ((size_t)b * LSEQ + row0 + r) * DM + g * 8);
    }
    #pragma unroll
    for (int it = 0; it < 8; it++) {
        int idx = it * 256 + tid;
        int r = idx >> 3, g8 = idx & 7;
        cp_async16(Ms + r * 512 + (((uint32_t)(g8 ^ (r & 7))) << 4),
                   g_m1h + ((size_t)b * DM + r) * DM + g8 * 8);
    }
    cp_commit();
    // groups 1..3: Ms chunks 1..3
    #pragma unroll
    for (int ch = 1; ch < 4; ch++) {
        #pragma unroll
        for (int it = 0; it < 8; it++) {
            int idx = it * 256 + tid;
            int r = idx >> 3, g8 = idx & 7;
            cp_async16(Ms + r * 512 + (((uint32_t)(8 * ch + (g8 ^ (r & 7)))) << 4),
                       g_m1h + ((size_t)b * DM + r) * DM + (8 * ch + g8) * 8);
        }
        cp_commit();
    }

    uint32_t ocp[32][2];
    #pragma unroll
    for (int j = 0; j < 32; j++) { ocp[j][0] = 0u; ocp[j][1] = 0u; }
    const int ar = m0 + lr;

#define YCHUNK(C)                                                               \
    _Pragma("unroll")                                                           \
    for (int kl = 0; kl < 4; kl++) {                                            \
        const int k16 = 4 * (C) + kl;                                           \
        uint32_t aq[4];                                                         \
        ldsm_x4(Xs + ar * 512 + ((((uint32_t)(2 * k16 + lh)) ^ (ar & 7)) << 4), aq); \
        _Pragma("unroll")                                                       \
        for (int nt = 0; nt < 16; nt++) {                                       \
            int rn = 16 * nt + lr;                                              \
            uint32_t bk[4];                                                     \
            ldsm_x4(Ms + rn * 512 + ((((uint32_t)(2 * k16 + lh)) ^ (rn & 7)) << 4), bk); \
            mma_f16(ocp[2*nt],     aq, bk[0], bk[2]);                           \
            mma_f16(ocp[2*nt + 1], aq, bk[1], bk[3]);                           \
        }                                                                       \
    }

    CP_WAIT(3); __syncthreads();
    YCHUNK(0)
    CP_WAIT(2); __syncthreads();
    YCHUNK(1)
    CP_WAIT(1); __syncthreads();
    YCHUNK(2)
    CP_WAIT(0); __syncthreads();
    YCHUNK(3)
#undef YCHUNK

    // ---- epilogue: x from Xs smem, pe from table ----
    const int rl = m0 + lq, rh = rl + 8;
    const int rlo = row0 + rl, rhi = row0 + rh;
    const float* c0p = g_c0 + b * DM;
    const uint32_t xrl = Xs + (uint32_t)rl * 512 + (uint32_t)lc * 4;
    const uint32_t xrh = Xs + (uint32_t)rh * 512 + (uint32_t)lc * 4;
    const uint32_t swl = (uint32_t)(rl & 7), swh = (uint32_t)(rh & 7);

    float d1l = 0.f, d2l = 0.f, d3l = 0.f;
    float d1h = 0.f, d2h = 0.f, d3h = 0.f;
    float2 xl2[32], xh2[32];
    #pragma unroll
    for (int j = 0; j < 32; j++) {
        int c = 8 * j + 2 * lc;
        float2 cv = *reinterpret_cast<const float2*>(c0p + c);
        uint32_t hv;
        asm volatile("ld.shared.b32 %0, [%1];" : "=r"(hv)
                     : "r"(xrl + (((uint32_t)j ^ swl) << 4)));
        float2 xv = __half22float2(*reinterpret_cast<__half2*>(&hv));
        xl2[j] = xv;
        float2 o2 = __half22float2(*reinterpret_cast<__half2*>(&ocp[j][0]));
        d1l += cv.x * xv.x + cv.y * xv.y;
        d2l += xv.x * o2.x + xv.y * o2.y;
        d3l += xv.x * xv.x + xv.y * xv.y;
        asm volatile("ld.shared.b32 %0, [%1];" : "=r"(hv)
                     : "r"(xrh + (((uint32_t)j ^ swh) << 4)));
        float2 xw = __half22float2(*reinterpret_cast<__half2*>(&hv));
        xh2[j] = xw;
        float2 o2h = __half22float2(*reinterpret_cast<__half2*>(&ocp[j][1]));
        d1h += cv.x * xw.x + cv.y * xw.y;
        d2h += xw.x * o2h.x + xw.y * o2h.y;
        d3h += xw.x * xw.x + xw.y * xw.y;
    }
    #pragma unroll
    for (int m = 1; m < 4; m <<= 1) {
        d1l += __shfl_xor_sync(0xffffffffu, d1l, m);
        d2l += __shfl_xor_sync(0xffffffffu, d2l, m);
        d3l += __shfl_xor_sync(0xffffffffu, d3l, m);
        d1h += __shfl_xor_sync(0xffffffffu, d1h, m);
        d2h += __shfl_xor_sync(0xffffffffu, d2h, m);
        d3h += __shfl_xor_sync(0xffffffffu, d3h, m);
    }
    const float s0v = g_s0[b];
    float sl = d3l, esl = __expf(0.5f * sl), wil = __expf(-0.5f * sl);
    float denl = s0v + d1l + 0.5f * d2l + (esl - wil * (1.f + sl + 0.5f * sl * sl));
    float nfl  = esl - wil * (1.f + sl);
    float il = 1.f / denl;
    float sh = d3h, esh = __expf(0.5f * sh), wih = __expf(-0.5f * sh);
    float denh = s0v + d1h + 0.5f * d2h + (esh - wih * (1.f + sh + 0.5f * sh * sh));
    float nfh  = esh - wih * (1.f + sh);
    float ih = 1.f / denh;

    float* olo = out + ((size_t)b * LSEQ + rlo) * DM;
    float* ohi = out + ((size_t)b * LSEQ + rhi) * DM;
    const float* plo = g_pe + (size_t)rlo * DM;
    const float* phi = g_pe + (size_t)rhi * DM;

    #pragma unroll
    for (int j = 0; j < 32; j++) {
        int c = 8 * j + 2 * lc;
        float2 cv = *reinterpret_cast<const float2*>(c0p + c);
        {
            float2 pe = *reinterpret_cast<const float2*>(plo + c);
            float2 o2 = __half22float2(*reinterpret_cast<__half2*>(&ocp[j][0]));
            float2 xv = xl2[j];
            float2 ov;
            ov.x = xv.x + pe.x + (cv.x + o2.x + nfl * xv.x) * il;
            ov.y = xv.y + pe.y + (cv.y + o2.y + nfl * xv.y) * il;
            *reinterpret_cast<float2*>(olo + c) = ov;
        }
        {
            float2 pe = *reinterpret_cast<const float2*>(phi + c);
            float2 o2 = __half22float2(*reinterpret_cast<__half2*>(&ocp[j][1]));
            float2 xv = xh2[j];
            float2 ov;
            ov.x = xv.x + pe.x + (cv.x + o2.x + nfh * xv.x) * ih;
            ov.y = xv.y + pe.y + (cv.y + o2.y + nfh * xv.y) * ih;
            *reinterpret_cast<float2*>(ohi + c) = ov;
        }
    }
}

// ================= launcher =================
extern "C" void kernel_launch(void* const* d_in, const int* in_sizes, int n_in,
                              void* d_out, int out_size)
{
    const float* x = (const float*)d_in[0];
    float* out = (float*)d_out;
    const int B = in_sizes[0] / (LSEQ * DM);

    cudaFuncSetAttribute(prep_kernel,
                         cudaFuncAttributeMaxDynamicSharedMemorySize, K1_SMEM);
    prep_kernel<<<dim3(LSEQ / 64, B), 256, K1_SMEM>>>(x);

    cudaFuncSetAttribute(gemmM1_kernel,
                         cudaFuncAttributeMaxDynamicSharedMemorySize, G_SMEM);
    gemmM1_kernel<<<dim3(KS2, 2, B), 256, G_SMEM>>>();

    reduceM1_kernel<<<dim3(DM + 1, B), 256>>>();

    cudaFuncSetAttribute(yepi_kernel,
                         cudaFuncAttributeMaxDynamicSharedMemorySize, G_SMEM);
    yepi_kernel<<<dim3(LSEQ / 128, B), 256, G_SMEM>>>(out);
}

// round 17
// speedup vs baseline: 1.0089x; 1.0089x over previous
#include <cuda_runtime.h>
#include <cuda_fp16.h>
#include <cstdint>

#define LSEQ 4096
#define DM   256
#define BMAX 4
#define KS2  8

// -------- scratch globals --------
__device__ __align__(16) __half g_xh [BMAX * LSEQ * DM];   // fp16 x   [b][l][d]
__device__ __align__(16) __half g_wxt[BMAX * DM * LSEQ];   // fp16 w*x [b][d][l]
__device__ float  g_w  [BMAX * LSEQ];
__device__ float  g_c0p[BMAX * 64 * DM];                   // c0 partials per 64-row slab
__device__ float  g_s0p[BMAX * 64];
__device__ float  g_c0 [BMAX * DM];
__device__ float  g_s0 [BMAX];
__device__ float  g_m1p[(size_t)KS2 * BMAX * DM * DM];     // M1 partials (8.4 MB)
__device__ __align__(16) __half g_m1h[BMAX * DM * DM];     // M1 fp16 (symmetric)
__device__ __align__(16) float g_pe[LSEQ * DM];            // PE table (batch-independent)

#define C_FREQ  (-0.035977892078032f)
#define INV_2PI ( 0.15915494309189535f)
#define PI2_HI  ( 6.28125f)
#define PI2_LO  ( 1.9353071795864769e-3f)

// ---------------- asm helpers ----------------
__device__ __forceinline__ uint32_t smem_u32(const void* p) {
    uint32_t a;
    asm("{ .reg .u64 t; cvta.to.shared.u64 t, %1; cvt.u32.u64 %0, t; }" : "=r"(a) : "l"(p));
    return a;
}
__device__ __forceinline__ void cp_async16(uint32_t dst, const void* src) {
    asm volatile("cp.async.cg.shared.global [%0], [%1], 16;" :: "r"(dst), "l"(src) : "memory");
}
__device__ __forceinline__ void cp_commit() { asm volatile("cp.async.commit_group;" ::: "memory"); }
__device__ __forceinline__ void cp_wait0()  { asm volatile("cp.async.wait_group 0;" ::: "memory"); }

__device__ __forceinline__ void ldsm_x4(uint32_t addr, uint32_t r[4]) {
    asm volatile("ldmatrix.sync.aligned.m8n8.x4.shared.b16 {%0,%1,%2,%3}, [%4];"
        : "=r"(r[0]), "=r"(r[1]), "=r"(r[2]), "=r"(r[3]) : "r"(addr));
}
__device__ __forceinline__ void ldsm_x4t(uint32_t addr, uint32_t r[4]) {
    asm volatile("ldmatrix.sync.aligned.m8n8.x4.trans.shared.b16 {%0,%1,%2,%3}, [%4];"
        : "=r"(r[0]), "=r"(r[1]), "=r"(r[2]), "=r"(r[3]) : "r"(addr));
}
__device__ __forceinline__ void mma_f32(float c[4], const uint32_t a[4],
                                        uint32_t b0, uint32_t b1) {
    asm volatile("mma.sync.aligned.m16n8k16.row.col.f32.f16.f16.f32 "
        "{%0,%1,%2,%3}, {%4,%5,%6,%7}, {%8,%9}, {%0,%1,%2,%3};"
        : "+f"(c[0]), "+f"(c[1]), "+f"(c[2]), "+f"(c[3])
        : "r"(a[0]), "r"(a[1]), "r"(a[2]), "r"(a[3]), "r"(b0), "r"(b1));
}
__device__ __forceinline__ uint32_t pack2f16(float lo, float hi) {
    uint32_t r;
    asm("cvt.rn.f16x2.f32 %0, %1, %2;" : "=r"(r) : "f"(hi), "f"(lo));
    return r;
}

// ========== K1: fused conv + transpose + w + c0/s0 partials + PE table ==========
#define K1_SMEM (64 * 264 * 2 + 64 * 4)
__global__ __launch_bounds__(256) void prep_kernel(const float* __restrict__ x) {
    extern __shared__ char smem[];
    __half* ths = reinterpret_cast<__half*>(smem);
    float*  ws  = reinterpret_cast<float*>(smem + 64 * 264 * 2);
    const int tid = threadIdx.x, wid = tid >> 5, lane = tid & 31;
    const int b = blockIdx.y, bx = blockIdx.x, l0 = bx * 64;
    const float* xs = x + ((size_t)b * LSEQ + l0) * DM;
    __half* xho = g_xh + ((size_t)b * LSEQ + l0) * DM;

    #pragma unroll
    for (int it = 0; it < 8; it++) {
        int r = it * 8 + wid;
        const float4* src = reinterpret_cast<const float4*>(xs + (size_t)r * DM);
        float4 a = src[lane * 2], c = src[lane * 2 + 1];
        uint4 v;
        v.x = pack2f16(a.x, a.y); v.y = pack2f16(a.z, a.w);
        v.z = pack2f16(c.x, c.y); v.w = pack2f16(c.z, c.w);
        *reinterpret_cast<uint4*>(ths + r * 264 + lane * 8) = v;
        reinterpret_cast<uint4*>(xho + (size_t)r * DM)[lane] = v;
        float s = a.x*a.x + a.y*a.y + a.z*a.z + a.w*a.w
                + c.x*c.x + c.y*c.y + c.z*c.z + c.w*c.w;
        #pragma unroll
        for (int m = 16; m > 0; m >>= 1) s += __shfl_xor_sync(0xffffffffu, s, m);
        if (lane == 0) {
            float w = __expf(-0.5f * s);
            ws[r] = w;
            g_w[b * LSEQ + l0 + r] = w;
        }
    }
    __syncthreads();

    const int d = tid;
    __half* dst = g_wxt + ((size_t)b * DM + d) * LSEQ + l0;
    float c0part = 0.f;
    #pragma unroll
    for (int q = 0; q < 4; q++) {
        uint32_t pk2[8];
        #pragma unroll
        for (int i = 0; i < 8; i++) {
            int l = q * 16 + 2 * i;
            float f0 = __half2float(ths[(l)     * 264 + d]) * ws[l];
            float f1 = __half2float(ths[(l + 1) * 264 + d]) * ws[l + 1];
            c0part += f0 + f1;
            pk2[i] = pack2f16(f0, f1);
        }
        reinterpret_cast<uint4*>(dst + q * 16)[0] = make_uint4(pk2[0], pk2[1], pk2[2], pk2[3]);
        reinterpret_cast<uint4*>(dst + q * 16)[1] = make_uint4(pk2[4], pk2[5], pk2[6], pk2[7]);
    }
    g_c0p[((size_t)b * 64 + bx) * DM + d] = c0part;

    if (wid == 0) {
        float s = ws[lane] + ws[lane + 32];
        #pragma unroll
        for (int m = 16; m > 0; m >>= 1) s += __shfl_xor_sync(0xffffffffu, s, m);
        if (lane == 0) g_s0p[b * 64 + bx] = s;
    }

    if (b == 0) {      // PE table
        float wf = __expf(C_FREQ * (float)(d & ~1));
        float* pp = g_pe + (size_t)l0 * DM + d;
        #pragma unroll 4
        for (int l = 0; l < 64; l++) {
            float ang = (float)(l0 + l) * wf;
            float k = rintf(ang * INV_2PI);
            float rr = fmaf(-k, PI2_HI, ang); rr = fmaf(-k, PI2_LO, rr);
            pp[(size_t)l * DM] = (d & 1) ? __cosf(rr) : __sinf(rr);
        }
    }
}

// ========== K2: M1 partial = (w X)^T X over 2 chunks of 256 keys ==========
#define G_SMEM 196608
__global__ __launch_bounds__(256, 1) void gemmM1_kernel() {
    extern __shared__ char smem[];
    const uint32_t sb = smem_u32(smem);
    const int tid = threadIdx.x, wid = tid >> 5, lane = tid & 31;
    const int ks = blockIdx.x, half = blockIdx.y, b = blockIdx.z;
    const int lr = lane & 15, lh = lane >> 4, lq = lane >> 2, lc = lane & 3;

    const int wa = (wid & 3) * 64;
    const int wn = (wid >> 2) * 64;
    float acc[4][8][4];
    #pragma unroll
    for (int mt = 0; mt < 4; mt++)
        #pragma unroll
        for (int f = 0; f < 8; f++)
            #pragma unroll
            for (int q = 0; q < 4; q++) acc[mt][f][q] = 0.f;

    const uint32_t As = sb, Bs = sb + 131072;

    for (int sub = 0; sub < 2; sub++) {
        const int jc = (ks * 2 + sub) * 256;
        if (sub) __syncthreads();
        #pragma unroll
        for (int it = 0; it < 32; it++) {
            int idx = it * 256 + tid;
            int r = idx >> 5, g = idx & 31;
            cp_async16(As + r * 512 + (((uint32_t)g ^ (r & 7)) << 4),
                       g_wxt + ((size_t)b * DM + r) * LSEQ + jc + g * 8);
        }
        #pragma unroll
        for (int it = 0; it < 16; it++) {
            int idx = it * 256 + tid;
            int r = idx >> 4, g = idx & 15;
            cp_async16(Bs + r * 256 + (((uint32_t)g ^ (r & 7)) << 4),
                       g_xh + ((size_t)b * LSEQ + jc + r) * DM + half * 128 + g * 8);
        }
        cp_commit(); cp_wait0();
        __syncthreads();

        #pragma unroll
        for (int k16 = 0; k16 < 16; k16++) {
            uint32_t aq[4][4];
            #pragma unroll
            for (int mt = 0; mt < 4; mt++) {
                int ar = wa + 16 * mt + lr;
                ldsm_x4(As + ar * 512 + ((((uint32_t)(2 * k16 + lh)) ^ (ar & 7)) << 4), aq[mt]);
            }
            #pragma unroll
            for (int nt = 0; nt < 4; nt++) {
                int rv = 16 * k16 + lr;
                int cb = (wn >> 3) + 2 * nt + lh;
                uint32_t bv[4];
                ldsm_x4t(Bs + rv * 256 + (((uint32_t)cb ^ (rv & 7)) << 4), bv);
                #pragma unroll
                for (int mt = 0; mt < 4; mt++) {
                    mma_f32(acc[mt][2*nt],     aq[mt], bv[0], bv[1]);
                    mma_f32(acc[mt][2*nt + 1], aq[mt], bv[2], bv[3]);
                }
            }
        }
    }

    #pragma unroll
    for (int mt = 0; mt < 4; mt++) {
        int r0 = wa + 16 * mt + lq;
        #pragma unroll
        for (int f = 0; f < 8; f++) {
            int col = half * 128 + wn + 8 * f + 2 * lc;
            size_t base = (((size_t)ks * BMAX + b) * DM + r0) * DM + col;
            *reinterpret_cast<float2*>(g_m1p + base) =
                make_float2(acc[mt][f][0], acc[mt][f][1]);
            *reinterpret_cast<float2*>(g_m1p + base + (size_t)8 * DM) =
                make_float2(acc[mt][f][2], acc[mt][f][3]);
        }
    }
}

// ========== K3: reduce M1 partials -> fp16, plus c0 and s0 ==========
__global__ void reduceM1_kernel() {
    int xb = blockIdx.x, b = blockIdx.y, tid = threadIdx.x;
    if (xb < DM) {
        float s = 0.f;
        #pragma unroll
        for (int ks = 0; ks < KS2; ks++)
            s += g_m1p[(((size_t)ks * BMAX + b) * DM + xb) * DM + tid];
        g_m1h[((size_t)b * DM + xb) * DM + tid] = __float2half(s);
    } else {
        float s = 0.f;
        #pragma unroll
        for (int k = 0; k < 64; k++)
            s += g_c0p[((size_t)b * 64 + k) * DM + tid];
        g_c0[b * DM + tid] = s;
        if (tid < 32) {
            float t = g_s0p[b * 64 + tid] + g_s0p[b * 64 + 32 + tid];
            #pragma unroll
            for (int m = 16; m > 0; m >>= 1) t += __shfl_xor_sync(0xffffffffu, t, m);
            if (tid == 0) g_s0[b] = t;
        }
    }
}

// ========== K4: Y = X M1 + epilogue (PE table, x from smem) ==========
__global__ __launch_bounds__(256, 1) void yepi_kernel(float* __restrict__ out)
{
    extern __shared__ char smem[];
    const uint32_t sb = smem_u32(smem);
    const int tid = threadIdx.x, wid = tid >> 5, lane = tid & 31;
    const int b = blockIdx.y, row0 = blockIdx.x * 128, m0 = wid * 16;
    const int lr = lane & 15, lh = lane >> 4, lq = lane >> 2, lc = lane & 3;
    const uint32_t Xs = sb, Ms = sb + 65536;

    #pragma unroll
    for (int it = 0; it < 16; it++) {
        int idx = it * 256 + tid;
        int r = idx >> 5, g = idx & 31;
        cp_async16(Xs + r * 512 + (((uint32_t)g ^ (r & 7)) << 4),
                   g_xh + ((size_t)b * LSEQ + row0 + r) * DM + g * 8);
    }
    #pragma unroll
    for (int it = 0; it < 32; it++) {
        int idx = it * 256 + tid;
        int r = idx >> 5, g = idx & 31;
        cp_async16(Ms + r * 512 + (((uint32_t)g ^ (r & 7)) << 4),
                   g_m1h + ((size_t)b * DM + r) * DM + g * 8);
    }
    cp_commit(); cp_wait0();
    __syncthreads();

    float oc[32][4];
    #pragma unroll
    for (int j = 0; j < 32; j++)
        #pragma unroll
        for (int q = 0; q < 4; q++) oc[j][q] = 0.f;

    const int ar = m0 + lr;
    #pragma unroll
    for (int k16 = 0; k16 < 16; k16++) {
        uint32_t aq[4];
        ldsm_x4(Xs + ar * 512 + ((((uint32_t)(2 * k16 + lh)) ^ (ar & 7)) << 4), aq);
        #pragma unroll
        for (int nt = 0; nt < 16; nt++) {
            int rn = 16 * nt + lr;
            uint32_t bk[4];
            ldsm_x4(Ms + rn * 512 + ((((uint32_t)(2 * k16 + lh)) ^ (rn & 7)) << 4), bk);
            mma_f32(oc[2*nt],     aq, bk[0], bk[2]);
            mma_f32(oc[2*nt + 1], aq, bk[1], bk[3]);
        }
    }

    // ---- epilogue: x from Xs smem, pe from table ----
    const int rl = m0 + lq, rh = rl + 8;
    const int rlo = row0 + rl, rhi = row0 + rh;
    const float* c0p = g_c0 + b * DM;
    const uint32_t xrl = Xs + (uint32_t)rl * 512 + (uint32_t)lc * 4;
    const uint32_t xrh = Xs + (uint32_t)rh * 512 + (uint32_t)lc * 4;
    const uint32_t swl = (uint32_t)(rl & 7), swh = (uint32_t)(rh & 7);

    float d1l = 0.f, d2l = 0.f, d3l = 0.f;
    float d1h = 0.f, d2h = 0.f, d3h = 0.f;
    #pragma unroll
    for (int j = 0; j < 32; j++) {
        int c = 8 * j + 2 * lc;
        float2 cv = *reinterpret_cast<const float2*>(c0p + c);
        uint32_t hv;
        asm volatile("ld.shared.b32 %0, [%1];" : "=r"(hv)
                     : "r"(xrl + (((uint32_t)j ^ swl) << 4)));
        float2 xv = __half22float2(*reinterpret_cast<__half2*>(&hv));
        d1l += cv.x * xv.x + cv.y * xv.y;
        d2l += xv.x * oc[j][0] + xv.y * oc[j][1];
        d3l += xv.x * xv.x + xv.y * xv.y;
        asm volatile("ld.shared.b32 %0, [%1];" : "=r"(hv)
                     : "r"(xrh + (((uint32_t)j ^ swh) << 4)));
        float2 xw = __half22float2(*reinterpret_cast<__half2*>(&hv));
        d1h += cv.x * xw.x + cv.y * xw.y;
        d2h += xw.x * oc[j][2] + xw.y * oc[j][3];
        d3h += xw.x * xw.x + xw.y * xw.y;
    }
    #pragma unroll
    for (int m = 1; m < 4; m <<= 1) {
        d1l += __shfl_xor_sync(0xffffffffu, d1l, m);
        d2l += __shfl_xor_sync(0xffffffffu, d2l, m);
        d3l += __shfl_xor_sync(0xffffffffu, d3l, m);
        d1h += __shfl_xor_sync(0xffffffffu, d1h, m);
        d2h += __shfl_xor_sync(0xffffffffu, d2h, m);
        d3h += __shfl_xor_sync(0xffffffffu, d3h, m);
    }
    const float s0v = g_s0[b];
    float sl = d3l, esl = __expf(0.5f * sl), wil = __expf(-0.5f * sl);
    float denl = s0v + d1l + 0.5f * d2l + (esl - wil * (1.f + sl + 0.5f * sl * sl));
    float nfl  = esl - wil * (1.f + sl);
    float il = 1.f / denl;
    float sh = d3h, esh = __expf(0.5f * sh), wih = __expf(-0.5f * sh);
    float denh = s0v + d1h + 0.5f * d2h + (esh - wih * (1.f + sh + 0.5f * sh * sh));
    float nfh  = esh - wih * (1.f + sh);
    float ih = 1.f / denh;

    float* olo = out + ((size_t)b * LSEQ + rlo) * DM;
    float* ohi = out + ((size_t)b * LSEQ + rhi) * DM;
    const float* plo = g_pe + (size_t)rlo * DM;
    const float* phi = g_pe + (size_t)rhi * DM;

    #pragma unroll
    for (int j = 0; j < 32; j++) {
        int c = 8 * j + 2 * lc;
        float2 cv = *reinterpret_cast<const float2*>(c0p + c);
        uint32_t hv;
        {
            asm volatile("ld.shared.b32 %0, [%1];" : "=r"(hv)
                         : "r"(xrl + (((uint32_t)j ^ swl) << 4)));
            float2 xv = __half22float2(*reinterpret_cast<__half2*>(&hv));
            float2 pe = *reinterpret_cast<const float2*>(plo + c);
            float2 ov;
            ov.x = xv.x + pe.x + (cv.x + oc[j][0] + nfl * xv.x) * il;
            ov.y = xv.y + pe.y + (cv.y + oc[j][1] + nfl * xv.y) * il;
            *reinterpret_cast<float2*>(olo + c) = ov;
        }
        {
            asm volatile("ld.shared.b32 %0, [%1];" : "=r"(hv)
                         : "r"(xrh + (((uint32_t)j ^ swh) << 4)));
            float2 xw = __half22float2(*reinterpret_cast<__half2*>(&hv));
            float2 pe = *reinterpret_cast<const float2*>(phi + c);
            float2 ov;
            ov.x = xw.x + pe.x + (cv.x + oc[j][2] + nfh * xw.x) * ih;
            ov.y = xw.y + pe.y + (cv.y + oc[j][3] + nfh * xw.y) * ih;
            *reinterpret_cast<float2*>(ohi + c) = ov;
        }
    }
}

// ================= launcher =================
extern "C" void kernel_launch(void* const* d_in, const int* in_sizes, int n_in,
                              void* d_out, int out_size)
{
    const float* x = (const float*)d_in[0];
    float* out = (float*)d_out;
    const int B = in_sizes[0] / (LSEQ * DM);

    cudaFuncSetAttribute(prep_kernel,
                         cudaFuncAttributeMaxDynamicSharedMemorySize, K1_SMEM);
    prep_kernel<<<dim3(LSEQ / 64, B), 256, K1_SMEM>>>(x);

    cudaFuncSetAttribute(gemmM1_kernel,
                         cudaFuncAttributeMaxDynamicSharedMemorySize, G_SMEM);
    gemmM1_kernel<<<dim3(KS2, 2, B), 256, G_SMEM>>>();

    reduceM1_kernel<<<dim3(DM + 1, B), 256>>>();

    cudaFuncSetAttribute(yepi_kernel,
                         cudaFuncAttributeMaxDynamicSharedMemorySize, G_SMEM);
    yepi_kernel<<<dim3(LSEQ / 128, B), 256, G_SMEM>>>(out);
}